// round 9
// baseline (speedup 1.0000x reference)
#include <cuda_runtime.h>
#include <math.h>

#define Nn 4096
#define Ee 8192
#define Mm 128
#define ND 128
#define ED 64
#define PQ 16
#define NP (Nn*PQ)
#define LAYERS 4
#define TAU 0.25f
#define FRIC 0.1f
#define MAXD 32

// ---------------- device scratch (no allocation allowed) ----------------
__device__ float g_a[Nn], g_c[Nn], g_avt[Nn], g_avu[Nn];
__device__ float g_pd0[Nn], g_pwu[Nn], g_pn[Nn], g_qd0[Nn], g_Wn[Nn];
__device__ int   g_mol[Nn];
__device__ int   g_cnt[Nn];            // zero at k1 entry; reset in kF
__device__ int   g_adjT[MAXD * Nn];    // [slot][node] -> other-node id (coalesced)
__device__ float g_wincT[MAXD * Nn];   // [slot][node] -> edge weight
__device__ int   g_slotU[Ee], g_slotV[Ee];
__device__ float g_p0[NP], g_q0[NP];
__device__ float g_suA[Nn], g_suB[Nn], g_cumA[Nn], g_cumB[Nn], g_cumG[Nn];
__device__ float g_zubA[Nn], g_atpA[Nn], g_wS[Nn], g_wG[Nn];
__device__ float g_Gm[LAYERS*Mm], g_Sm[LAYERS*Mm], g_h[Mm], g_d[Mm], g_S[LAYERS];

__device__ __forceinline__ float warp_sum(float v) {
#pragma unroll
    for (int o = 16; o; o >>= 1) v += __shfl_xor_sync(0xffffffffu, v, o);
    return v;
}
__device__ __forceinline__ float sigmoidf(float x) { return 1.f / (1.f + expf(-x)); }
__device__ __forceinline__ float softplusf(float x) { return fmaxf(x, 0.f) + log1pf(expf(-fabsf(x))); }

// ======== k1: node setup (warp/node) + mol ids + adjacency + accumulator zeroing ========
__global__ void k1(const float* __restrict__ vf, const float* __restrict__ mnm,
                   const int* __restrict__ us, const int* __restrict__ vs,
                   const float* __restrict__ We, const float* __restrict__ Wp,
                   const float* __restrict__ bp, const float* __restrict__ Wt,
                   const float* __restrict__ Wu)
{
    int tid  = blockIdx.x * blockDim.x + threadIdx.x;   // 131072 threads
    int lane = threadIdx.x & 31;
    int n    = tid >> 5;                                 // warp -> node

    if (tid < Nn) g_Wn[tid] = 0.f;
    if (tid < LAYERS*Mm) { g_Gm[tid] = 0.f; g_Sm[tid] = 0.f; }
    if (tid < Mm) { g_h[tid] = 0.f; g_d[tid] = 0.f; }
    if (tid < LAYERS) g_S[tid] = 0.f;

    for (int idx = tid; idx < Mm * Nn; idx += 131072)
        if (mnm[idx] > 0.5f) g_mol[idx & (Nn - 1)] = idx >> 12;

    for (int e = tid; e < Ee; e += 131072) {
        int u = us[e], v = vs[e];
        int s1 = atomicAdd(&g_cnt[u], 1);
        if (s1 < MAXD) g_adjT[s1 * Nn + u] = v;
        g_slotU[e] = s1;
        if (u != v) {
            int s2 = atomicAdd(&g_cnt[v], 1);
            if (s2 < MAXD) g_adjT[s2 * Nn + v] = u;
            g_slotV[e] = s2;
        }
    }

    float v0 = vf[n*ND+lane], v1 = vf[n*ND+lane+32], v2 = vf[n*ND+lane+64], v3 = vf[n*ND+lane+96];
    float sa = warp_sum(v0*We[lane]     + v1*We[lane+32]     + v2*We[lane+64]     + v3*We[lane+96]);
    float sc = warp_sum(v0*We[192+lane] + v1*We[192+lane+32] + v2*We[192+lane+64] + v3*We[192+lane+96]);
    float st = warp_sum(v0*Wt[lane]     + v1*Wt[lane+32]     + v2*Wt[lane+64]     + v3*Wt[lane+96]);
    float su = warp_sum(v0*Wu[lane]     + v1*Wu[lane+32]     + v2*Wu[lane+64]     + v3*Wu[lane+96]);

    float pk = 0.f;
#pragma unroll
    for (int k = 0; k < PQ; k++) {
        float s = warp_sum(v0*Wp[lane*PQ+k] + v1*Wp[(lane+32)*PQ+k] +
                           v2*Wp[(lane+64)*PQ+k] + v3*Wp[(lane+96)*PQ+k]);
        if (lane == k) pk = tanhf(s + bp[k]);
    }
    float pd0 = warp_sum(lane < PQ ? pk * Wt[ND+lane] : 0.f);
    float pwu = warp_sum(lane < PQ ? pk * Wu[ND+lane] : 0.f);
    float pn  = warp_sum(lane < PQ ? pk * pk          : 0.f);
    if (lane < PQ) g_p0[n*PQ+lane] = pk;
    if (lane == 0) {
        g_a[n] = sa; g_c[n] = sc; g_avt[n] = st; g_avu[n] = su;
        g_pd0[n] = pd0; g_pwu[n] = pwu; g_pn[n] = pn;
    }
}

// ======== k2: edge weights (warp/edge) ========
__global__ void k2(const float* __restrict__ ef,
                   const int* __restrict__ us, const int* __restrict__ vs,
                   const float* __restrict__ We, const float* __restrict__ be)
{
    int e    = (blockIdx.x * blockDim.x + threadIdx.x) >> 5;
    int lane = threadIdx.x & 31;
    if (e >= Ee) return;
    float s = ef[e*ED+lane] * We[128+lane] + ef[e*ED+32+lane] * We[160+lane];
    s = warp_sum(s);
    if (lane == 0) {
        int u = us[e], v = vs[e];
        float w = sigmoidf(g_a[u] + g_c[v] + s + be[0]);
        int s1 = g_slotU[e];
        if (s1 < MAXD) g_wincT[s1 * Nn + u] = w;
        if (u != v) {
            int s2 = g_slotV[e];
            if (s2 < MAXD) g_wincT[s2 * Nn + v] = w;
            atomicAdd(&g_Wn[u], w);
            atomicAdd(&g_Wn[v], w);
        }
    }
}

// ======== k3: q0 = tanh((e@v)@Wq + bq), qd0 (warp/node) ========
__global__ void k3(const float* __restrict__ vf, const float* __restrict__ Wq,
                   const float* __restrict__ bq, const float* __restrict__ Wu)
{
    int n    = (blockIdx.x * blockDim.x + threadIdx.x) >> 5;
    int lane = threadIdx.x & 31;
    float x0 = vf[n*ND+lane], x1 = vf[n*ND+lane+32], x2 = vf[n*ND+lane+64], x3 = vf[n*ND+lane+96];
    float Wn = g_Wn[n];
    float e0 = Wn*x0, e1 = Wn*x1, e2 = Wn*x2, e3 = Wn*x3;
    int deg = min(g_cnt[n], MAXD);
    for (int j = 0; j < deg; j++) {
        int   o = g_adjT[j*Nn + n];
        float w = g_wincT[j*Nn + n];
        e0 += w * vf[o*ND+lane];
        e1 += w * vf[o*ND+lane+32];
        e2 += w * vf[o*ND+lane+64];
        e3 += w * vf[o*ND+lane+96];
    }
    float qk = 0.f;
#pragma unroll
    for (int k = 0; k < PQ; k++) {
        float s = warp_sum(e0*Wq[lane*PQ+k] + e1*Wq[(lane+32)*PQ+k] +
                           e2*Wq[(lane+64)*PQ+k] + e3*Wq[(lane+96)*PQ+k]);
        if (lane == k) qk = tanhf(s + bq[k]);
    }
    float qd0 = warp_sum(lane < PQ ? qk * Wu[ND+lane] : 0.f);
    if (lane < PQ) g_q0[n*PQ+lane] = qk;
    if (lane == 0) g_qd0[n] = qd0;
}

// ======== kZ: zub gather + layer-1 locals (thread/node, coalesced slots) ========
__global__ void kZ(const float* __restrict__ Wt)
{
    int n = blockIdx.x * blockDim.x + threadIdx.x;
    float nWt = 0.f;
#pragma unroll
    for (int k = 0; k < PQ; k++) { float b = Wt[ND+k]; nWt += b*b; }

    int deg = min(g_cnt[n], MAXD);
    float s = g_Wn[n] * g_qd0[n];
    for (int j = 0; j < deg; j++) {
        int o = g_adjT[j*Nn + n];
        s += g_wincT[j*Nn + n] * g_qd0[o];
    }
    float zub = g_avu[n] + s;
    float atp = g_avt[n] + g_pd0[n];
    g_zubA[n] = zub; g_atpA[n] = atp;

    float st1 = sigmoidf(atp), su1 = sigmoidf(zub);
    g_suA[n] = su1; g_cumA[n] = st1;
    g_wS[n] = 4.f * st1;
    atomicAdd(&g_Sm[g_mol[n]], st1);

    float sl = st1*st1*nWt - 2.f*st1*g_pd0[n];
    sl = warp_sum(sl);
    __shared__ float sh[4];
    if ((threadIdx.x & 31) == 0) sh[threadIdx.x >> 5] = sl;
    __syncthreads();
    if (threadIdx.x == 0) {
        float t = 0.f;
        for (int i = 0; i < 4; i++) t += sh[i];
        atomicAdd(&g_S[0], t);
    }
}

// ======== kL: one layer phase (ph=1..4); gathers (su_ph, cumSt_ph) ========
__global__ void kL(const float* __restrict__ Wt, const float* __restrict__ Wu, int ph)
{
    int n = blockIdx.x * blockDim.x + threadIdx.x;
    float nWt = 0.f, nWu = 0.f, dTU = 0.f;
#pragma unroll
    for (int k = 0; k < PQ; k++) {
        float a = Wu[ND+k], b = Wt[ND+k];
        nWu += a*a; nWt += b*b; dTU += a*b;
    }
    const float* suIN  = (ph & 1) ? g_suA  : g_suB;
    float*       suOUT = (ph & 1) ? g_suB  : g_suA;
    const float* cumIN = (ph & 1) ? g_cumA : g_cumB;
    float*       cumOUT= (ph & 1) ? g_cumB : g_cumA;

    int deg = min(g_cnt[n], MAXD);
    float Wn = g_Wn[n];
    float suSelf = suIN[n], cumSelf = cumIN[n];
    float gg = Wn * suSelf, G = Wn * cumSelf;
    for (int j = 0; j < deg; j++) {
        int   o = g_adjT[j*Nn + n];
        float w = g_wincT[j*Nn + n];
        gg += w * suIN[o];
        G  += w * cumIN[o];
    }
    int mol = g_mol[n];
    atomicAdd(&g_Gm[(ph-1)*Mm + mol], gg);
    float cumG = ((ph == 1) ? 0.f : g_cumG[n]) + gg;
    g_cumG[n] = cumG;
    if (ph == 1) g_wG[n] = 4.f * gg;
    else         g_wG[n] += (float)(5 - ph) * gg;

    float sl = 0.f;
    if (ph < 4) {
        float zt = g_atpA[n] - TAU * (dTU * cumG + FRIC * nWt * cumSelf);
        float st = sigmoidf(zt);
        float zu = g_zubA[n] + TAU * dTU * G;
        float su = sigmoidf(zu);
        suOUT[n] = su;
        cumOUT[n] = cumSelf + st;
        g_wS[n] += (float)(4 - ph) * st;
        atomicAdd(&g_Sm[ph*Mm + mol], st);
        float alpha = st + TAU * FRIC * cumSelf;
        float beta  = TAU * cumG;
        sl = alpha*alpha*nWt + beta*beta*nWu + 2.f*alpha*beta*dTU
           - 2.f*alpha*g_pd0[n] - 2.f*beta*g_pwu[n];
        if (ph == 3) {   // zt/zu/st here are layer-4 values
            atomicAdd(&g_h[mol], softplusf(zt) + softplusf(zu));
            atomicAdd(&g_d[mol], st * st);
        }
    }
    sl = warp_sum(sl);
    __shared__ float sh[4];
    if ((threadIdx.x & 31) == 0) sh[threadIdx.x >> 5] = sl;
    __syncthreads();
    if (threadIdx.x == 0 && ph < 4) {
        float t = 0.f;
        for (int i = 0; i < 4; i++) t += sh[i];
        atomicAdd(&g_S[ph], t);
    }
}

// ======== kF: outputs + scalars + counter reset ========
__global__ void kF(const float* __restrict__ Wt, const float* __restrict__ Wu,
                   float* __restrict__ out)
{
    int idx = blockIdx.x * blockDim.x + threadIdx.x;  // 131072 = 2*NP
    if (idx < NP) {
        int n = idx >> 4, k = idx & 15;
        out[idx] = 0.2f * (5.f*g_p0[idx] - (TAU*FRIC)*g_wS[n]*Wt[ND+k] - TAU*g_wG[n]*Wu[ND+k]);
    } else {
        int id2 = idx - NP, n = id2 >> 4, k = id2 & 15;
        out[idx] = 0.2f * (5.f*g_q0[id2] + TAU*g_wS[n]*Wt[ND+k]);
    }
    if (idx < Nn) g_cnt[idx] = 0;

    if (blockIdx.x == 0) {
        int t = threadIdx.x, lane = t & 31;
        float nWt = 0.f, nWu = 0.f, dTU = 0.f;
#pragma unroll
        for (int k = 0; k < PQ; k++) {
            float a = Wu[ND+k], b = Wt[ND+k];
            nWu += a*a; nWt += b*b; dTU += a*b;
        }
        __shared__ float sh[8];
        __shared__ float shPN;
        float pn = 0.f;
        for (int n = t; n < Nn; n += 256) pn += g_pn[n];
        pn = warp_sum(pn);
        if (lane == 0) sh[t >> 5] = pn;
        __syncthreads();
        if (t == 0) {
            float s = 0.f;
            for (int i = 0; i < 8; i++) s += sh[i];
            shPN = s;
        }
        __syncthreads();
        if (t < 32) {
            float cT = 0.f;
            for (int i = 0; i < LAYERS; i++) {
                float term = 0.f;
                for (int m = lane; m < Mm; m += 32) {
                    float Gm = g_Gm[i*Mm+m], Sm = g_Sm[i*Mm+m];
                    term += Gm*Gm*nWu + 2.f*FRIC*Gm*Sm*dTU + FRIC*FRIC*Sm*Sm*nWt;
                }
                term = warp_sum(term);
                cT += TAU * sqrtf(term);
            }
            if (lane == 0) {
                float sT = 0.f;
                for (int i = 0; i < LAYERS; i++) sT += sqrtf(g_S[i] + shPN);
                out[2*NP + 0] = sT;
                out[2*NP + 1] = cT;
            }
        }
        if (t < Mm) {
            out[2*NP + 2 + t]      = g_h[t];
            out[2*NP + 2 + Mm + t] = g_d[t] * nWt;
        }
    }
}

extern "C" void kernel_launch(void* const* d_in, const int* in_sizes, int n_in,
                              void* d_out, int out_size)
{
    const float* vf  = (const float*)d_in[0];
    const float* ef  = (const float*)d_in[1];
    const int*   us  = (const int*)  d_in[2];
    const int*   vs  = (const int*)  d_in[3];
    const float* mnm = (const float*)d_in[4];
    const float* We  = (const float*)d_in[8];
    const float* be  = (const float*)d_in[9];
    const float* Wp  = (const float*)d_in[10];
    const float* bp  = (const float*)d_in[11];
    const float* Wq  = (const float*)d_in[12];
    const float* bq  = (const float*)d_in[13];
    const float* Wt  = (const float*)d_in[14];
    const float* Wu  = (const float*)d_in[15];
    float* out = (float*)d_out;

    k1<<<512, 256>>>(vf, mnm, us, vs, We, Wp, bp, Wt, Wu);
    k2<<<1024, 256>>>(ef, us, vs, We, be);
    k3<<<512, 256>>>(vf, Wq, bq, Wu);
    kZ<<<32, 128>>>(Wt);
    kL<<<32, 128>>>(Wt, Wu, 1);
    kL<<<32, 128>>>(Wt, Wu, 2);
    kL<<<32, 128>>>(Wt, Wu, 3);
    kL<<<32, 128>>>(Wt, Wu, 4);
    kF<<<512, 256>>>(Wt, Wu, out);
}

// round 10
// speedup vs baseline: 1.0983x; 1.0983x over previous
#include <cuda_runtime.h>
#include <math.h>

#define Nn 4096
#define Ee 8192
#define Mm 128
#define ND 128
#define ED 64
#define PQ 16
#define NP (Nn*PQ)
#define LAYERS 4
#define TAU 0.25f
#define FRIC 0.1f
#define MAXD 32
#define GB_NB 32
#define GB_BT 128

// ---------------- device scratch (no allocation allowed) ----------------
__device__ float g_a[Nn], g_c[Nn], g_avt[Nn], g_avu[Nn];
__device__ float g_pd0[Nn], g_pwu[Nn], g_pn[Nn], g_qd0[Nn], g_Wn[Nn];
__device__ int   g_mol[Nn];
__device__ int   g_cnt[Nn];            // zero at k1 entry; reset in kBig
__device__ int   g_adjT[MAXD * Nn];    // [slot][node] -> other-node id (coalesced)
__device__ float g_wincT[MAXD * Nn];   // [slot][node] -> edge weight
__device__ int   g_slotU[Ee], g_slotV[Ee];
__device__ float g_p0[NP], g_q0[NP];
__device__ float g_suA[Nn], g_suB[Nn], g_cumA[Nn], g_cumB[Nn];
__device__ float g_Gm[LAYERS*Mm], g_Sm[LAYERS*Mm], g_h[Mm], g_d[Mm], g_S[LAYERS];
__device__ unsigned g_bar;             // monotonic grid-barrier counter

__device__ __forceinline__ float warp_sum(float v) {
#pragma unroll
    for (int o = 16; o; o >>= 1) v += __shfl_xor_sync(0xffffffffu, v, o);
    return v;
}
__device__ __forceinline__ float sigmoidf(float x) { return 1.f / (1.f + expf(-x)); }
__device__ __forceinline__ float softplusf(float x) { return fmaxf(x, 0.f) + log1pf(expf(-fabsf(x))); }

// grid barrier across GB_NB blocks; monotonic counter, no reset needed
// (each launch consumes exactly 5*GB_NB increments; invariant % GB_NB == 0).
__device__ __forceinline__ void gsync() {
    __threadfence();
    __syncthreads();
    if (threadIdx.x == 0) {
        unsigned t = atomicAdd(&g_bar, 1u);
        unsigned target = (t / GB_NB + 1u) * GB_NB;
        while (*((volatile unsigned*)&g_bar) < target) __nanosleep(32);
    }
    __syncthreads();
    __threadfence();
}

// ======== k1: node setup (warp/node) + mol ids + adjacency + accumulator zeroing ========
__global__ void k1(const float* __restrict__ vf, const float* __restrict__ mnm,
                   const int* __restrict__ us, const int* __restrict__ vs,
                   const float* __restrict__ We, const float* __restrict__ Wp,
                   const float* __restrict__ bp, const float* __restrict__ Wt,
                   const float* __restrict__ Wu)
{
    int tid  = blockIdx.x * blockDim.x + threadIdx.x;   // 131072 threads
    int lane = threadIdx.x & 31;
    int n    = tid >> 5;                                 // warp -> node

    if (tid < Nn) g_Wn[tid] = 0.f;
    if (tid < LAYERS*Mm) { g_Gm[tid] = 0.f; g_Sm[tid] = 0.f; }
    if (tid < Mm) { g_h[tid] = 0.f; g_d[tid] = 0.f; }
    if (tid < LAYERS) g_S[tid] = 0.f;

    for (int idx = tid; idx < Mm * Nn; idx += 131072)
        if (mnm[idx] > 0.5f) g_mol[idx & (Nn - 1)] = idx >> 12;

    for (int e = tid; e < Ee; e += 131072) {
        int u = us[e], v = vs[e];
        int s1 = atomicAdd(&g_cnt[u], 1);
        if (s1 < MAXD) g_adjT[s1 * Nn + u] = v;
        g_slotU[e] = s1;
        if (u != v) {
            int s2 = atomicAdd(&g_cnt[v], 1);
            if (s2 < MAXD) g_adjT[s2 * Nn + v] = u;
            g_slotV[e] = s2;
        }
    }

    float v0 = vf[n*ND+lane], v1 = vf[n*ND+lane+32], v2 = vf[n*ND+lane+64], v3 = vf[n*ND+lane+96];
    float sa = warp_sum(v0*We[lane]     + v1*We[lane+32]     + v2*We[lane+64]     + v3*We[lane+96]);
    float sc = warp_sum(v0*We[192+lane] + v1*We[192+lane+32] + v2*We[192+lane+64] + v3*We[192+lane+96]);
    float st = warp_sum(v0*Wt[lane]     + v1*Wt[lane+32]     + v2*Wt[lane+64]     + v3*Wt[lane+96]);
    float su = warp_sum(v0*Wu[lane]     + v1*Wu[lane+32]     + v2*Wu[lane+64]     + v3*Wu[lane+96]);

    float pk = 0.f;
#pragma unroll
    for (int k = 0; k < PQ; k++) {
        float s = warp_sum(v0*Wp[lane*PQ+k] + v1*Wp[(lane+32)*PQ+k] +
                           v2*Wp[(lane+64)*PQ+k] + v3*Wp[(lane+96)*PQ+k]);
        if (lane == k) pk = tanhf(s + bp[k]);
    }
    float pd0 = warp_sum(lane < PQ ? pk * Wt[ND+lane] : 0.f);
    float pwu = warp_sum(lane < PQ ? pk * Wu[ND+lane] : 0.f);
    float pn  = warp_sum(lane < PQ ? pk * pk          : 0.f);
    if (lane < PQ) g_p0[n*PQ+lane] = pk;
    if (lane == 0) {
        g_a[n] = sa; g_c[n] = sc; g_avt[n] = st; g_avu[n] = su;
        g_pd0[n] = pd0; g_pwu[n] = pwu; g_pn[n] = pn;
    }
}

// ======== k2: edge weights (warp/edge) ========
__global__ void k2(const float* __restrict__ ef,
                   const int* __restrict__ us, const int* __restrict__ vs,
                   const float* __restrict__ We, const float* __restrict__ be)
{
    int e    = (blockIdx.x * blockDim.x + threadIdx.x) >> 5;
    int lane = threadIdx.x & 31;
    if (e >= Ee) return;
    float s = ef[e*ED+lane] * We[128+lane] + ef[e*ED+32+lane] * We[160+lane];
    s = warp_sum(s);
    if (lane == 0) {
        int u = us[e], v = vs[e];
        float w = sigmoidf(g_a[u] + g_c[v] + s + be[0]);
        int s1 = g_slotU[e];
        if (s1 < MAXD) g_wincT[s1 * Nn + u] = w;
        if (u != v) {
            int s2 = g_slotV[e];
            if (s2 < MAXD) g_wincT[s2 * Nn + v] = w;
            atomicAdd(&g_Wn[u], w);
            atomicAdd(&g_Wn[v], w);
        }
    }
}

// ======== k3: q0 = tanh((e@v)@Wq + bq), qd0 (warp/node) ========
__global__ void k3(const float* __restrict__ vf, const float* __restrict__ Wq,
                   const float* __restrict__ bq, const float* __restrict__ Wu)
{
    int n    = (blockIdx.x * blockDim.x + threadIdx.x) >> 5;
    int lane = threadIdx.x & 31;
    float x0 = vf[n*ND+lane], x1 = vf[n*ND+lane+32], x2 = vf[n*ND+lane+64], x3 = vf[n*ND+lane+96];
    float Wn = g_Wn[n];
    float e0 = Wn*x0, e1 = Wn*x1, e2 = Wn*x2, e3 = Wn*x3;
    int deg = min(g_cnt[n], MAXD);
    for (int j = 0; j < deg; j++) {
        int   o = g_adjT[j*Nn + n];
        float w = g_wincT[j*Nn + n];
        e0 += w * vf[o*ND+lane];
        e1 += w * vf[o*ND+lane+32];
        e2 += w * vf[o*ND+lane+64];
        e3 += w * vf[o*ND+lane+96];
    }
    float qk = 0.f;
#pragma unroll
    for (int k = 0; k < PQ; k++) {
        float s = warp_sum(e0*Wq[lane*PQ+k] + e1*Wq[(lane+32)*PQ+k] +
                           e2*Wq[(lane+64)*PQ+k] + e3*Wq[(lane+96)*PQ+k]);
        if (lane == k) qk = tanhf(s + bq[k]);
    }
    float qd0 = warp_sum(lane < PQ ? qk * Wu[ND+lane] : 0.f);
    if (lane < PQ) g_q0[n*PQ+lane] = qk;
    if (lane == 0) g_qd0[n] = qd0;
}

// ======== kBig: zub + 4 layers + outputs, one launch, 5 grid barriers ========
__global__ void __launch_bounds__(GB_BT, 1)
kBig(const float* __restrict__ Wt, const float* __restrict__ Wu, float* __restrict__ out)
{
    const int n = blockIdx.x * GB_BT + threadIdx.x;   // 0..4095, thread per node
    const int lane = threadIdx.x & 31;

    float nWt = 0.f, nWu = 0.f, dTU = 0.f;
    float wt2[PQ], wu2[PQ];
#pragma unroll
    for (int k = 0; k < PQ; k++) {
        float a = Wu[ND+k], b = Wt[ND+k];
        wt2[k] = b; wu2[k] = a;
        nWu += a*a; nWt += b*b; dTU += a*b;
    }

    const int   deg = min(g_cnt[n], MAXD);
    const int   mol = g_mol[n];
    const float Wn  = g_Wn[n];
    const float pd0 = g_pd0[n], pwu = g_pwu[n];

    // ---- P0: zub gather + layer-1 locals ----
    float s = Wn * g_qd0[n];
    for (int j = 0; j < deg; j++)
        s += g_wincT[j*Nn + n] * g_qd0[g_adjT[j*Nn + n]];
    const float zub = g_avu[n] + s;
    const float atp = g_avt[n] + pd0;

    float st = sigmoidf(atp), su = sigmoidf(zub);
    float cum = st;
    g_suA[n] = su; g_cumA[n] = cum;
    float wS = 4.f * st, wG = 0.f, cumG = 0.f;
    atomicAdd(&g_Sm[mol], st);
    {
        float sl = st*st*nWt - 2.f*st*pd0;
        sl = warp_sum(sl);
        if (lane == 0) atomicAdd(&g_S[0], sl);
    }
    gsync();  // 1

    // ---- P1..P4 ----
    for (int ph = 1; ph <= 4; ph++) {
        const float* suIN   = (ph & 1) ? g_suA  : g_suB;
        float*       suOUT  = (ph & 1) ? g_suB  : g_suA;
        const float* cumIN  = (ph & 1) ? g_cumA : g_cumB;
        float*       cumOUT = (ph & 1) ? g_cumB : g_cumA;

        float gg = Wn * su, G = Wn * cum;
        for (int j = 0; j < deg; j++) {
            int   o = g_adjT[j*Nn + n];
            float w = g_wincT[j*Nn + n];
            gg += w * suIN[o];
            G  += w * cumIN[o];
        }
        atomicAdd(&g_Gm[(ph-1)*Mm + mol], gg);
        cumG += gg;
        wG += (float)((ph == 1) ? 4 : (5 - ph)) * gg;

        if (ph < 4) {
            float zt = atp - TAU * (dTU * cumG + FRIC * nWt * cum);
            float stn = sigmoidf(zt);
            float zu = zub + TAU * dTU * G;
            float sun = sigmoidf(zu);
            suOUT[n] = sun;
            float cumn = cum + stn;
            cumOUT[n] = cumn;
            wS += (float)(4 - ph) * stn;
            atomicAdd(&g_Sm[ph*Mm + mol], stn);
            float alpha = stn + TAU * FRIC * cum;
            float beta  = TAU * cumG;
            float sl = alpha*alpha*nWt + beta*beta*nWu + 2.f*alpha*beta*dTU
                     - 2.f*alpha*pd0 - 2.f*beta*pwu;
            sl = warp_sum(sl);
            if (lane == 0) atomicAdd(&g_S[ph], sl);
            if (ph == 3) {   // zt/zu/stn are layer-4 values
                atomicAdd(&g_h[mol], softplusf(zt) + softplusf(zu));
                atomicAdd(&g_d[mol], stn * stn);
            }
            su = sun; cum = cumn;
        }
        gsync();  // 2..5
    }

    // ---- outputs: thread n writes its 16 p and 16 q values ----
    {
        float cp1 = -(TAU*FRIC) * wS, cp2 = -TAU * wG, cq = TAU * wS;
#pragma unroll
        for (int k = 0; k < PQ; k++) {
            out[n*PQ + k]      = 0.2f * (5.f*g_p0[n*PQ+k] + cp1*wt2[k] + cp2*wu2[k]);
            out[NP + n*PQ + k] = 0.2f * (5.f*g_q0[n*PQ+k] + cq*wt2[k]);
        }
    }
    g_cnt[n] = 0;

    // ---- block 0: scalars + h/d ----
    if (blockIdx.x == 0) {
        int t = threadIdx.x;
        __shared__ float sh[4];
        __shared__ float shPN;
        float pn = 0.f;
        for (int i = t; i < Nn; i += GB_BT) pn += g_pn[i];
        pn = warp_sum(pn);
        if (lane == 0) sh[t >> 5] = pn;
        __syncthreads();
        if (t == 0) shPN = sh[0] + sh[1] + sh[2] + sh[3];
        __syncthreads();
        if (t < 32) {
            float cT = 0.f;
            for (int i = 0; i < LAYERS; i++) {
                float term = 0.f;
                for (int m = lane; m < Mm; m += 32) {
                    float Gm = g_Gm[i*Mm+m], Sm = g_Sm[i*Mm+m];
                    term += Gm*Gm*nWu + 2.f*FRIC*Gm*Sm*dTU + FRIC*FRIC*Sm*Sm*nWt;
                }
                term = warp_sum(term);
                cT += TAU * sqrtf(term);
            }
            if (lane == 0) {
                float sT = 0.f;
                for (int i = 0; i < LAYERS; i++) sT += sqrtf(g_S[i] + shPN);
                out[2*NP + 0] = sT;
                out[2*NP + 1] = cT;
            }
        }
        out[2*NP + 2 + t]      = g_h[t];          // t covers 0..127 = Mm
        out[2*NP + 2 + Mm + t] = g_d[t] * nWt;
    }
}

extern "C" void kernel_launch(void* const* d_in, const int* in_sizes, int n_in,
                              void* d_out, int out_size)
{
    const float* vf  = (const float*)d_in[0];
    const float* ef  = (const float*)d_in[1];
    const int*   us  = (const int*)  d_in[2];
    const int*   vs  = (const int*)  d_in[3];
    const float* mnm = (const float*)d_in[4];
    const float* We  = (const float*)d_in[8];
    const float* be  = (const float*)d_in[9];
    const float* Wp  = (const float*)d_in[10];
    const float* bp  = (const float*)d_in[11];
    const float* Wq  = (const float*)d_in[12];
    const float* bq  = (const float*)d_in[13];
    const float* Wt  = (const float*)d_in[14];
    const float* Wu  = (const float*)d_in[15];
    float* out = (float*)d_out;

    k1<<<512, 256>>>(vf, mnm, us, vs, We, Wp, bp, Wt, Wu);
    k2<<<1024, 256>>>(ef, us, vs, We, be);
    k3<<<512, 256>>>(vf, Wq, bq, Wu);
    kBig<<<GB_NB, GB_BT>>>(Wt, Wu, out);
}

// round 11
// speedup vs baseline: 1.1542x; 1.0509x over previous
#include <cuda_runtime.h>
#include <math.h>

#define Nn 4096
#define Ee 8192
#define Mm 128
#define ND 128
#define ED 64
#define PQ 16
#define NP (Nn*PQ)
#define LAYERS 4
#define TAU 0.25f
#define FRIC 0.1f
#define MAXD 32
#define GB_NB 32
#define GB_BT 128

// ---------------- device scratch (no allocation allowed) ----------------
__device__ float g_a[Nn], g_c[Nn], g_avt[Nn], g_avu[Nn];
__device__ float g_pd0[Nn], g_pwu[Nn], g_pn[Nn], g_qd0[Nn], g_Wn[Nn];
__device__ int   g_mol[Nn];
__device__ int   g_cnt[Nn];            // zero at k1 entry; reset in kBig
__device__ int   g_adjT[MAXD * Nn];    // [slot][node] -> other-node id (coalesced)
__device__ float g_wincT[MAXD * Nn];   // [slot][node] -> edge weight
__device__ int   g_slotU[Ee], g_slotV[Ee];
__device__ float g_p0[NP], g_q0[NP];
__device__ float2 g_scA[Nn], g_scB[Nn];   // packed (su, cumSt)
__device__ float g_Gm[LAYERS*Mm], g_Sm[LAYERS*Mm], g_h[Mm], g_d[Mm], g_S[LAYERS];
__device__ unsigned g_bar;             // monotonic grid-barrier counter

__device__ __forceinline__ float warp_sum(float v) {
#pragma unroll
    for (int o = 16; o; o >>= 1) v += __shfl_xor_sync(0xffffffffu, v, o);
    return v;
}
__device__ __forceinline__ float sigmoidf(float x) { return 1.f / (1.f + expf(-x)); }
// fast variants for kBig (MUFU; plenty of precision headroom vs 1e-3 threshold)
__device__ __forceinline__ float fsigmoid(float x) { return 1.f / (1.f + __expf(-x)); }
__device__ __forceinline__ float fsoftplus(float x) { return fmaxf(x, 0.f) + __logf(1.f + __expf(-fabsf(x))); }

// grid barrier across GB_NB blocks; monotonic counter, no reset needed
// (each launch consumes exactly 5*GB_NB increments; invariant % GB_NB == 0).
__device__ __forceinline__ void gsync() {
    __threadfence();
    __syncthreads();
    if (threadIdx.x == 0) {
        unsigned t = atomicAdd(&g_bar, 1u);
        unsigned target = (t / GB_NB + 1u) * GB_NB;
        while (*((volatile unsigned*)&g_bar) < target) __nanosleep(32);
    }
    __syncthreads();
    __threadfence();
}

// ======== k1: node setup (warp/node) + mol ids + adjacency + accumulator zeroing ========
__global__ void k1(const float* __restrict__ vf, const float* __restrict__ mnm,
                   const int* __restrict__ us, const int* __restrict__ vs,
                   const float* __restrict__ We, const float* __restrict__ Wp,
                   const float* __restrict__ bp, const float* __restrict__ Wt,
                   const float* __restrict__ Wu)
{
    int tid  = blockIdx.x * blockDim.x + threadIdx.x;   // 131072 threads
    int lane = threadIdx.x & 31;
    int n    = tid >> 5;                                 // warp -> node

    if (tid < Nn) g_Wn[tid] = 0.f;
    if (tid < LAYERS*Mm) { g_Gm[tid] = 0.f; g_Sm[tid] = 0.f; }
    if (tid < Mm) { g_h[tid] = 0.f; g_d[tid] = 0.f; }
    if (tid < LAYERS) g_S[tid] = 0.f;

    for (int idx = tid; idx < Mm * Nn; idx += 131072)
        if (mnm[idx] > 0.5f) g_mol[idx & (Nn - 1)] = idx >> 12;

    for (int e = tid; e < Ee; e += 131072) {
        int u = us[e], v = vs[e];
        int s1 = atomicAdd(&g_cnt[u], 1);
        if (s1 < MAXD) g_adjT[s1 * Nn + u] = v;
        g_slotU[e] = s1;
        if (u != v) {
            int s2 = atomicAdd(&g_cnt[v], 1);
            if (s2 < MAXD) g_adjT[s2 * Nn + v] = u;
            g_slotV[e] = s2;
        }
    }

    float v0 = vf[n*ND+lane], v1 = vf[n*ND+lane+32], v2 = vf[n*ND+lane+64], v3 = vf[n*ND+lane+96];
    float sa = warp_sum(v0*We[lane]     + v1*We[lane+32]     + v2*We[lane+64]     + v3*We[lane+96]);
    float sc = warp_sum(v0*We[192+lane] + v1*We[192+lane+32] + v2*We[192+lane+64] + v3*We[192+lane+96]);
    float st = warp_sum(v0*Wt[lane]     + v1*Wt[lane+32]     + v2*Wt[lane+64]     + v3*Wt[lane+96]);
    float su = warp_sum(v0*Wu[lane]     + v1*Wu[lane+32]     + v2*Wu[lane+64]     + v3*Wu[lane+96]);

    float pk = 0.f;
#pragma unroll
    for (int k = 0; k < PQ; k++) {
        float s = warp_sum(v0*Wp[lane*PQ+k] + v1*Wp[(lane+32)*PQ+k] +
                           v2*Wp[(lane+64)*PQ+k] + v3*Wp[(lane+96)*PQ+k]);
        if (lane == k) pk = tanhf(s + bp[k]);
    }
    float pd0 = warp_sum(lane < PQ ? pk * Wt[ND+lane] : 0.f);
    float pwu = warp_sum(lane < PQ ? pk * Wu[ND+lane] : 0.f);
    float pn  = warp_sum(lane < PQ ? pk * pk          : 0.f);
    if (lane < PQ) g_p0[n*PQ+lane] = pk;
    if (lane == 0) {
        g_a[n] = sa; g_c[n] = sc; g_avt[n] = st; g_avu[n] = su;
        g_pd0[n] = pd0; g_pwu[n] = pwu; g_pn[n] = pn;
    }
}

// ======== k2: edge weights (warp/edge) ========
__global__ void k2(const float* __restrict__ ef,
                   const int* __restrict__ us, const int* __restrict__ vs,
                   const float* __restrict__ We, const float* __restrict__ be)
{
    int e    = (blockIdx.x * blockDim.x + threadIdx.x) >> 5;
    int lane = threadIdx.x & 31;
    if (e >= Ee) return;
    float s = ef[e*ED+lane] * We[128+lane] + ef[e*ED+32+lane] * We[160+lane];
    s = warp_sum(s);
    if (lane == 0) {
        int u = us[e], v = vs[e];
        float w = sigmoidf(g_a[u] + g_c[v] + s + be[0]);
        int s1 = g_slotU[e];
        if (s1 < MAXD) g_wincT[s1 * Nn + u] = w;
        if (u != v) {
            int s2 = g_slotV[e];
            if (s2 < MAXD) g_wincT[s2 * Nn + v] = w;
            atomicAdd(&g_Wn[u], w);
            atomicAdd(&g_Wn[v], w);
        }
    }
}

// ======== k3: q0 = tanh((e@v)@Wq + bq), qd0 (warp/node) ========
__global__ void k3(const float* __restrict__ vf, const float* __restrict__ Wq,
                   const float* __restrict__ bq, const float* __restrict__ Wu)
{
    int n    = (blockIdx.x * blockDim.x + threadIdx.x) >> 5;
    int lane = threadIdx.x & 31;
    float x0 = vf[n*ND+lane], x1 = vf[n*ND+lane+32], x2 = vf[n*ND+lane+64], x3 = vf[n*ND+lane+96];
    float Wn = g_Wn[n];
    float e0 = Wn*x0, e1 = Wn*x1, e2 = Wn*x2, e3 = Wn*x3;
    int deg = min(g_cnt[n], MAXD);
    for (int j = 0; j < deg; j++) {
        int   o = g_adjT[j*Nn + n];
        float w = g_wincT[j*Nn + n];
        e0 += w * vf[o*ND+lane];
        e1 += w * vf[o*ND+lane+32];
        e2 += w * vf[o*ND+lane+64];
        e3 += w * vf[o*ND+lane+96];
    }
    float qk = 0.f;
#pragma unroll
    for (int k = 0; k < PQ; k++) {
        float s = warp_sum(e0*Wq[lane*PQ+k] + e1*Wq[(lane+32)*PQ+k] +
                           e2*Wq[(lane+64)*PQ+k] + e3*Wq[(lane+96)*PQ+k]);
        if (lane == k) qk = tanhf(s + bq[k]);
    }
    float qd0 = warp_sum(lane < PQ ? qk * Wu[ND+lane] : 0.f);
    if (lane < PQ) g_q0[n*PQ+lane] = qk;
    if (lane == 0) g_qd0[n] = qd0;
}

// ======== kBig: zub + 4 layers + outputs; SMEM-cached adjacency, float2 state ========
__global__ void __launch_bounds__(GB_BT, 1)
kBig(const float* __restrict__ Wt, const float* __restrict__ Wu, float* __restrict__ out)
{
    __shared__ unsigned short s_o[MAXD * GB_BT];  // [slot][thread] -> other node
    __shared__ float          s_w[MAXD * GB_BT];  // [slot][thread] -> weight
    __shared__ float sh[4];
    __shared__ float shPN;

    const int t = threadIdx.x;
    const int n = blockIdx.x * GB_BT + t;         // thread per node
    const int lane = t & 31;

    float nWt = 0.f, nWu = 0.f, dTU = 0.f;
    float wt2[PQ], wu2[PQ];
#pragma unroll
    for (int k = 0; k < PQ; k++) {
        float a = Wu[ND+k], b = Wt[ND+k];
        wt2[k] = b; wu2[k] = a;
        nWu += a*a; nWt += b*b; dTU += a*b;
    }

    const int   deg = min(g_cnt[n], MAXD);
    const int   mol = g_mol[n];
    const float Wn  = g_Wn[n];
    const float pd0 = g_pd0[n], pwu = g_pwu[n];

    // ---- prologue: cache adjacency in SMEM (own slots only; no sync needed) ----
    for (int j = 0; j < deg; j++) {
        s_o[j*GB_BT + t] = (unsigned short)g_adjT[j*Nn + n];
        s_w[j*GB_BT + t] = g_wincT[j*Nn + n];
    }

    // ---- P0: zub gather + layer-1 locals ----
    float s = Wn * g_qd0[n];
    for (int j = 0; j < deg; j++)
        s += s_w[j*GB_BT + t] * g_qd0[s_o[j*GB_BT + t]];
    const float zub = g_avu[n] + s;
    const float atp = g_avt[n] + pd0;

    float st = fsigmoid(atp), su = fsigmoid(zub);
    float cum = st;
    g_scA[n] = make_float2(su, cum);
    float wS = 4.f * st, wG = 0.f, cumG = 0.f;
    atomicAdd(&g_Sm[mol], st);
    {
        float sl = st*st*nWt - 2.f*st*pd0;
        sl = warp_sum(sl);
        if (lane == 0) atomicAdd(&g_S[0], sl);
    }
    gsync();  // 1

    // ---- P1..P4 ----
    for (int ph = 1; ph <= 4; ph++) {
        const float2* IN  = (ph & 1) ? g_scA : g_scB;
        float2*       OUT = (ph & 1) ? g_scB : g_scA;

        float gg = Wn * su, G = Wn * cum;
        for (int j = 0; j < deg; j++) {
            float  w  = s_w[j*GB_BT + t];
            float2 sc = IN[s_o[j*GB_BT + t]];
            gg += w * sc.x;
            G  += w * sc.y;
        }
        atomicAdd(&g_Gm[(ph-1)*Mm + mol], gg);
        cumG += gg;
        wG += (float)((ph == 1) ? 4 : (5 - ph)) * gg;

        if (ph < 4) {
            float zt = atp - TAU * (dTU * cumG + FRIC * nWt * cum);
            float stn = fsigmoid(zt);
            float zu = zub + TAU * dTU * G;
            float sun = fsigmoid(zu);
            float cumn = cum + stn;
            OUT[n] = make_float2(sun, cumn);
            wS += (float)(4 - ph) * stn;
            atomicAdd(&g_Sm[ph*Mm + mol], stn);
            float alpha = stn + TAU * FRIC * cum;
            float beta  = TAU * cumG;
            float sl = alpha*alpha*nWt + beta*beta*nWu + 2.f*alpha*beta*dTU
                     - 2.f*alpha*pd0 - 2.f*beta*pwu;
            sl = warp_sum(sl);
            if (lane == 0) atomicAdd(&g_S[ph], sl);
            if (ph == 3) {   // zt/zu/stn are layer-4 values
                atomicAdd(&g_h[mol], fsoftplus(zt) + fsoftplus(zu));
                atomicAdd(&g_d[mol], stn * stn);
            }
            su = sun; cum = cumn;
        }
        gsync();  // 2..5
    }

    // ---- outputs: thread n writes its 16 p and 16 q values ----
    {
        float cp1 = -(TAU*FRIC) * wS, cp2 = -TAU * wG, cq = TAU * wS;
#pragma unroll
        for (int k = 0; k < PQ; k++) {
            out[n*PQ + k]      = 0.2f * (5.f*g_p0[n*PQ+k] + cp1*wt2[k] + cp2*wu2[k]);
            out[NP + n*PQ + k] = 0.2f * (5.f*g_q0[n*PQ+k] + cq*wt2[k]);
        }
    }
    g_cnt[n] = 0;

    // ---- block 0: scalars + h/d ----
    if (blockIdx.x == 0) {
        float pn = 0.f;
        for (int i = t; i < Nn; i += GB_BT) pn += g_pn[i];
        pn = warp_sum(pn);
        if (lane == 0) sh[t >> 5] = pn;
        __syncthreads();
        if (t == 0) shPN = sh[0] + sh[1] + sh[2] + sh[3];
        __syncthreads();
        if (t < 32) {
            float cT = 0.f;
            for (int i = 0; i < LAYERS; i++) {
                float term = 0.f;
                for (int m = lane; m < Mm; m += 32) {
                    float Gm = g_Gm[i*Mm+m], Sm = g_Sm[i*Mm+m];
                    term += Gm*Gm*nWu + 2.f*FRIC*Gm*Sm*dTU + FRIC*FRIC*Sm*Sm*nWt;
                }
                term = warp_sum(term);
                cT += TAU * sqrtf(term);
            }
            if (lane == 0) {
                float sT = 0.f;
                for (int i = 0; i < LAYERS; i++) sT += sqrtf(g_S[i] + shPN);
                out[2*NP + 0] = sT;
                out[2*NP + 1] = cT;
            }
        }
        out[2*NP + 2 + t]      = g_h[t];          // t covers 0..127 = Mm
        out[2*NP + 2 + Mm + t] = g_d[t] * nWt;
    }
}

extern "C" void kernel_launch(void* const* d_in, const int* in_sizes, int n_in,
                              void* d_out, int out_size)
{
    const float* vf  = (const float*)d_in[0];
    const float* ef  = (const float*)d_in[1];
    const int*   us  = (const int*)  d_in[2];
    const int*   vs  = (const int*)  d_in[3];
    const float* mnm = (const float*)d_in[4];
    const float* We  = (const float*)d_in[8];
    const float* be  = (const float*)d_in[9];
    const float* Wp  = (const float*)d_in[10];
    const float* bp  = (const float*)d_in[11];
    const float* Wq  = (const float*)d_in[12];
    const float* bq  = (const float*)d_in[13];
    const float* Wt  = (const float*)d_in[14];
    const float* Wu  = (const float*)d_in[15];
    float* out = (float*)d_out;

    k1<<<512, 256>>>(vf, mnm, us, vs, We, Wp, bp, Wt, Wu);
    k2<<<1024, 256>>>(ef, us, vs, We, be);
    k3<<<512, 256>>>(vf, Wq, bq, Wu);
    kBig<<<GB_NB, GB_BT>>>(Wt, Wu, out);
}